// round 1
// baseline (speedup 1.0000x reference)
#include <cuda_runtime.h>
#include <cuda_bf16.h>
#include <math.h>

// Problem constants
#define BATCH 8
#define NPTS 4096
#define CH 128
#define KNN 9
#define MROWS (BATCH * NPTS)   // 32768
#define EPSBN 1e-5f

// GEMM tiling
#define BM 128
#define BN 128
#define BK 16

// ---------------- device scratch (no allocations allowed) ----------------
__device__ float g_S[(size_t)BATCH * NPTS * NPTS];   // 512 MB distance scores
__device__ float g_H[(size_t)MROWS * CH];            // h after fc1+BN
__device__ float g_Y[(size_t)MROWS * CH];            // pre-BN GEMM output (reused 3x)
__device__ float g_CAT[(size_t)MROWS * 2 * CH];      // [h, agg]
__device__ float g_HG[(size_t)MROWS * CH];           // after gcn BN+GELU
__device__ float g_rowsq[MROWS];
__device__ int   g_idx[MROWS * KNN];
__device__ float g_psum[256 * CH];
__device__ float g_psq[256 * CH];
__device__ float g_mean[CH];
__device__ float g_inv[CH];

// ---------------- generic SGEMM: Out[M x 128] = A[M x Kd] @ W[Kd x 128] + bias ----------------
__global__ __launch_bounds__(256) void sgemm_bias_kernel(
    const float* __restrict__ A, const float* __restrict__ W,
    const float* __restrict__ bias, float* __restrict__ Out, int Kd)
{
    __shared__ float As[BK][BM + 4];
    __shared__ float Ws[BK][BN];

    const int tid = threadIdx.x;            // 256 threads = 16x16
    const int m0  = blockIdx.x * BM;
    const int tr  = tid / 16;
    const int tc  = tid % 16;

    float acc[8][8];
#pragma unroll
    for (int i = 0; i < 8; i++)
#pragma unroll
        for (int j = 0; j < 8; j++) acc[i][j] = 0.0f;

    for (int k0 = 0; k0 < Kd; k0 += BK) {
        // A tile: 128 rows x 16 cols, stored transposed As[k][m]
#pragma unroll
        for (int i = 0; i < 2; i++) {
            int lin  = tid + i * 256;       // 0..511 float4 slots
            int row  = lin >> 2;            // 4 float4 per row
            int col4 = lin & 3;
            float4 v = *(const float4*)(A + (size_t)(m0 + row) * Kd + k0 + col4 * 4);
            As[col4 * 4 + 0][row] = v.x;
            As[col4 * 4 + 1][row] = v.y;
            As[col4 * 4 + 2][row] = v.z;
            As[col4 * 4 + 3][row] = v.w;
        }
        // W tile: 16 rows x 128 cols, natural layout
#pragma unroll
        for (int i = 0; i < 2; i++) {
            int lin = tid + i * 256;        // 512 float4: 16 rows x 32 f4
            int row = lin >> 5;
            int c4  = lin & 31;
            *(float4*)&Ws[row][c4 * 4] =
                *(const float4*)(W + (size_t)(k0 + row) * 128 + c4 * 4);
        }
        __syncthreads();

#pragma unroll
        for (int k = 0; k < BK; k++) {
            float a[8], b[8];
            *(float4*)(a)     = *(float4*)&As[k][tr * 8];
            *(float4*)(a + 4) = *(float4*)&As[k][tr * 8 + 4];
            *(float4*)(b)     = *(float4*)&Ws[k][tc * 8];
            *(float4*)(b + 4) = *(float4*)&Ws[k][tc * 8 + 4];
#pragma unroll
            for (int i = 0; i < 8; i++)
#pragma unroll
                for (int j = 0; j < 8; j++) acc[i][j] += a[i] * b[j];
        }
        __syncthreads();
    }

    float bv[8];
#pragma unroll
    for (int j = 0; j < 8; j++) bv[j] = bias[tc * 8 + j];
#pragma unroll
    for (int i = 0; i < 8; i++) {
        int m = m0 + tr * 8 + i;
        float* o = Out + (size_t)m * 128 + tc * 8;
#pragma unroll
        for (int j = 0; j < 8; j++) o[j] = acc[i][j] + bv[j];
    }
}

// ---------------- distance GEMM (NT): s[b][i][j] = rowsq[b][j] - 2 * h_i . h_j ----------------
__global__ __launch_bounds__(256) void dist_kernel(
    const float* __restrict__ H, const float* __restrict__ rowsq,
    float* __restrict__ S)
{
    __shared__ float As[BK][BM + 4];
    __shared__ float Bs[BK][BN + 4];

    const int tid = threadIdx.x;
    const int b   = blockIdx.z;
    const int i0  = blockIdx.y * BM;
    const int j0  = blockIdx.x * BN;
    const float* Hb = H + (size_t)b * NPTS * CH;
    const int tr = tid / 16;
    const int tc = tid % 16;

    float acc[8][8];
#pragma unroll
    for (int i = 0; i < 8; i++)
#pragma unroll
        for (int j = 0; j < 8; j++) acc[i][j] = 0.0f;

    for (int k0 = 0; k0 < CH; k0 += BK) {
#pragma unroll
        for (int i = 0; i < 2; i++) {
            int lin  = tid + i * 256;
            int row  = lin >> 2;
            int col4 = lin & 3;
            float4 va = *(const float4*)(Hb + (size_t)(i0 + row) * CH + k0 + col4 * 4);
            As[col4 * 4 + 0][row] = va.x;
            As[col4 * 4 + 1][row] = va.y;
            As[col4 * 4 + 2][row] = va.z;
            As[col4 * 4 + 3][row] = va.w;
            float4 vb = *(const float4*)(Hb + (size_t)(j0 + row) * CH + k0 + col4 * 4);
            Bs[col4 * 4 + 0][row] = vb.x;
            Bs[col4 * 4 + 1][row] = vb.y;
            Bs[col4 * 4 + 2][row] = vb.z;
            Bs[col4 * 4 + 3][row] = vb.w;
        }
        __syncthreads();

#pragma unroll
        for (int k = 0; k < BK; k++) {
            float a[8], b2[8];
            *(float4*)(a)      = *(float4*)&As[k][tr * 8];
            *(float4*)(a + 4)  = *(float4*)&As[k][tr * 8 + 4];
            *(float4*)(b2)     = *(float4*)&Bs[k][tc * 8];
            *(float4*)(b2 + 4) = *(float4*)&Bs[k][tc * 8 + 4];
#pragma unroll
            for (int i = 0; i < 8; i++)
#pragma unroll
                for (int j = 0; j < 8; j++) acc[i][j] += a[i] * b2[j];
        }
        __syncthreads();
    }

    float sq[8];
#pragma unroll
    for (int j = 0; j < 8; j++) sq[j] = rowsq[b * NPTS + j0 + tc * 8 + j];

#pragma unroll
    for (int i = 0; i < 8; i++) {
        int gi = i0 + tr * 8 + i;
        float* o = S + ((size_t)b * NPTS + gi) * NPTS + j0 + tc * 8;
        float v[8];
#pragma unroll
        for (int j = 0; j < 8; j++) v[j] = sq[j] - 2.0f * acc[i][j];
        *(float4*)(o)     = *(float4*)(v);
        *(float4*)(o + 4) = *(float4*)(v + 4);
    }
}

// ---------------- top-9 smallest per row (tie -> lower index, like top_k) ----------------
__global__ __launch_bounds__(256) void topk_kernel(
    const float* __restrict__ S, int* __restrict__ Idx)
{
    const int row = blockIdx.x;                  // 0..MROWS-1
    const float* s = S + (size_t)row * NPTS;
    const int tid = threadIdx.x;                 // 256

    unsigned long long best[KNN];
#pragma unroll
    for (int q = 0; q < KNN; q++) best[q] = 0xFFFFFFFFFFFFFFFFull;

    for (int j = tid; j < NPTS; j += 256) {
        float v = s[j];
        unsigned int bits = __float_as_uint(v);
        unsigned int k32 = (bits & 0x80000000u) ? ~bits : (bits | 0x80000000u);
        unsigned long long key = ((unsigned long long)k32 << 32) | (unsigned int)j;
        if (key < best[KNN - 1]) {
            int p = KNN - 1;
            while (p > 0 && best[p - 1] > key) { best[p] = best[p - 1]; p--; }
            best[p] = key;
        }
    }

    __shared__ unsigned long long sm[256 * KNN];
#pragma unroll
    for (int q = 0; q < KNN; q++) sm[tid * KNN + q] = best[q];
    __syncthreads();

    for (int stride = 128; stride >= 1; stride >>= 1) {
        if (tid < stride) {
            unsigned long long* A  = &sm[tid * KNN];
            unsigned long long* Bp = &sm[(tid + stride) * KNN];
            unsigned long long out[KNN];
            int ia = 0, ib = 0;
#pragma unroll
            for (int q = 0; q < KNN; q++)
                out[q] = (A[ia] <= Bp[ib]) ? A[ia++] : Bp[ib++];
#pragma unroll
            for (int q = 0; q < KNN; q++) A[q] = out[q];
        }
        __syncthreads();
    }

    if (tid < KNN) Idx[row * KNN + tid] = (int)(sm[tid] & 0xFFFFFFFFull);
}

// ---------------- max-relative aggregation + concat ----------------
__global__ __launch_bounds__(128) void agg_cat_kernel(
    const float* __restrict__ H, const int* __restrict__ Idx,
    float* __restrict__ CAT)
{
    const int row = blockIdx.x;
    const int b   = row >> 12;            // /4096
    const int c   = threadIdx.x;          // 128

    __shared__ int nb[KNN];
    if (c < KNN) nb[c] = Idx[row * KNN + c];
    __syncthreads();

    const float hv = H[(size_t)row * CH + c];
    const float* Hb = H + (size_t)b * NPTS * CH;
    float m = -INFINITY;
#pragma unroll
    for (int k = 0; k < KNN; k++)
        m = fmaxf(m, Hb[(size_t)nb[k] * CH + c] - hv);

    CAT[(size_t)row * (2 * CH) + c]      = hv;
    CAT[(size_t)row * (2 * CH) + CH + c] = m;
}

// ---------------- deterministic column stats (mean / inv-std) ----------------
__global__ __launch_bounds__(128) void colstats1_kernel(
    const float* __restrict__ Y, float* __restrict__ psum, float* __restrict__ psq)
{
    const int blk = blockIdx.x;          // 256 blocks x 128 rows
    const int c   = threadIdx.x;
    const float* p = Y + (size_t)blk * 128 * CH + c;
    float s = 0.0f, ss = 0.0f;
    for (int r = 0; r < 128; r++) {
        float v = p[(size_t)r * CH];
        s += v; ss += v * v;
    }
    psum[blk * CH + c] = s;
    psq[blk * CH + c]  = ss;
}

__global__ __launch_bounds__(128) void colstats2_kernel(
    const float* __restrict__ psum, const float* __restrict__ psq,
    float* __restrict__ mean, float* __restrict__ inv)
{
    const int c = threadIdx.x;
    float s = 0.0f, ss = 0.0f;
    for (int i = 0; i < 256; i++) { s += psum[i * CH + c]; ss += psq[i * CH + c]; }
    const float m = s * (1.0f / (float)MROWS);
    const float v = ss * (1.0f / (float)MROWS) - m * m;
    mean[c] = m;
    inv[c]  = rsqrtf(v + EPSBN);
}

// ---------------- BN apply variants ----------------
__global__ __launch_bounds__(128) void bn_apply_rowsq_kernel(
    const float* __restrict__ Y, const float* __restrict__ mean,
    const float* __restrict__ inv, const float* __restrict__ g,
    const float* __restrict__ be, float* __restrict__ H,
    float* __restrict__ rowsq)
{
    const int row = blockIdx.x;
    const int c   = threadIdx.x;
    const float y = Y[(size_t)row * CH + c];
    const float h = g[c] * (y - mean[c]) * inv[c] + be[c];
    H[(size_t)row * CH + c] = h;

    __shared__ float red[CH];
    red[c] = h * h;
    __syncthreads();
    for (int s = 64; s >= 1; s >>= 1) {
        if (c < s) red[c] += red[c + s];
        __syncthreads();
    }
    if (c == 0) rowsq[row] = red[0];
}

__global__ __launch_bounds__(256) void bn_gelu_kernel(
    const float* __restrict__ Y, const float* __restrict__ mean,
    const float* __restrict__ inv, const float* __restrict__ g,
    const float* __restrict__ be, float* __restrict__ O)
{
    const int i = blockIdx.x * 256 + threadIdx.x;
    const int c = i & (CH - 1);
    const float y = Y[i];
    const float h = g[c] * (y - mean[c]) * inv[c] + be[c];
    O[i] = 0.5f * h * (1.0f + erff(h * 0.70710678118654752f));
}

__global__ __launch_bounds__(256) void bn_res_kernel(
    const float* __restrict__ Y, const float* __restrict__ mean,
    const float* __restrict__ inv, const float* __restrict__ g,
    const float* __restrict__ be, const float* __restrict__ x,
    float* __restrict__ out)
{
    const int i = blockIdx.x * 256 + threadIdx.x;
    const int c = i & (CH - 1);
    const float y = Y[i];
    const float h = g[c] * (y - mean[c]) * inv[c] + be[c];
    out[i] = h + x[i];
}

// ---------------- launch ----------------
extern "C" void kernel_launch(void* const* d_in, const int* in_sizes, int n_in,
                              void* d_out, int out_size)
{
    const float* x   = (const float*)d_in[0];
    const float* W1  = (const float*)d_in[1];
    const float* b1  = (const float*)d_in[2];
    const float* g1  = (const float*)d_in[3];
    const float* be1 = (const float*)d_in[4];
    const float* Wg  = (const float*)d_in[5];
    const float* bg  = (const float*)d_in[6];
    const float* gg  = (const float*)d_in[7];
    const float* beg = (const float*)d_in[8];
    const float* W2  = (const float*)d_in[9];
    const float* b2  = (const float*)d_in[10];
    const float* g2  = (const float*)d_in[11];
    const float* be2 = (const float*)d_in[12];
    float* out = (float*)d_out;

    float *pS, *pH, *pY, *pCAT, *pHG, *prowsq, *ppsum, *ppsq, *pmean, *pinv;
    int* pidx;
    cudaGetSymbolAddress((void**)&pS, g_S);
    cudaGetSymbolAddress((void**)&pH, g_H);
    cudaGetSymbolAddress((void**)&pY, g_Y);
    cudaGetSymbolAddress((void**)&pCAT, g_CAT);
    cudaGetSymbolAddress((void**)&pHG, g_HG);
    cudaGetSymbolAddress((void**)&prowsq, g_rowsq);
    cudaGetSymbolAddress((void**)&pidx, g_idx);
    cudaGetSymbolAddress((void**)&ppsum, g_psum);
    cudaGetSymbolAddress((void**)&ppsq, g_psq);
    cudaGetSymbolAddress((void**)&pmean, g_mean);
    cudaGetSymbolAddress((void**)&pinv, g_inv);

    // ---- fc1 + BN ----
    sgemm_bias_kernel<<<MROWS / BM, 256>>>(x, W1, b1, pY, CH);
    colstats1_kernel<<<256, 128>>>(pY, ppsum, ppsq);
    colstats2_kernel<<<1, 128>>>(ppsum, ppsq, pmean, pinv);
    bn_apply_rowsq_kernel<<<MROWS, 128>>>(pY, pmean, pinv, g1, be1, pH, prowsq);

    // ---- KNN ----
    dist_kernel<<<dim3(NPTS / BN, NPTS / BM, BATCH), 256>>>(pH, prowsq, pS);
    topk_kernel<<<MROWS, 256>>>(pS, pidx);
    agg_cat_kernel<<<MROWS, 128>>>(pH, pidx, pCAT);

    // ---- graph MLP: [h, agg] @ Wg + BN + GELU ----
    sgemm_bias_kernel<<<MROWS / BM, 256>>>(pCAT, Wg, bg, pY, 2 * CH);
    colstats1_kernel<<<256, 128>>>(pY, ppsum, ppsq);
    colstats2_kernel<<<1, 128>>>(ppsum, ppsq, pmean, pinv);
    bn_gelu_kernel<<<(MROWS * CH) / 256, 256>>>(pY, pmean, pinv, gg, beg, pHG);

    // ---- fc2 + BN + residual ----
    sgemm_bias_kernel<<<MROWS / BM, 256>>>(pHG, W2, b2, pY, CH);
    colstats1_kernel<<<256, 128>>>(pY, ppsum, ppsq);
    colstats2_kernel<<<1, 128>>>(ppsum, ppsq, pmean, pinv);
    bn_res_kernel<<<(MROWS * CH) / 256, 256>>>(pY, pmean, pinv, g2, be2, x, out);
}